// round 15
// baseline (speedup 1.0000x reference)
#include <cuda_runtime.h>
#include <cuda_fp16.h>
#include <cstdint>
#include <math.h>

// Problem constants (fixed by the dataset)
#define NMAX 50000
#define EMAX 600000
#define FIN  64
#define HID  128

#define FUSE_BLOCKS 592        // 4 blocks/SM x 148 SMs, residency-guaranteed
#define FUSE_THREADS 256
#define GEMM_BLOCKS 592        // 2 CTAs/SM x 148 SMs x 2 waves exactly

// ---------------------------------------------------------------------------
// Scratch (device globals; no allocation allowed in kernel_launch)
// Replay invariants: g_cnt == 0, g_dis == 0, g_bar_count == 0 at every entry.
// ---------------------------------------------------------------------------
__device__ float    g_dis[NMAX];           // deg, then d^{-1/2}, then reset to 0
__device__ int      g_cnt[NMAX];           // in-degree histogram; reset to 0
__device__ int      g_cur[NMAX];           // scatter cursors (init from scan)
__device__ int      g_row[NMAX + 1];       // CSR row offsets (by dst)
__device__ int      g_blksum[256];         // scan chunk partials
__device__ int2     g_meta[EMAX];          // per-edge {src, w_bits} (CSR order)
__device__ __half   g_Xh[NMAX * FIN];      // fp16 copy of x (gather source only)
__device__ __half   g_S1h[NMAX * FIN];     // P x      (fp16 storage)
__device__ __half   g_S2h[NMAX * FIN];     // P^2 x    (fp16 storage)
__device__ float    g_S3[NMAX * FIN];      // P^3 x    (fp32)
// B operand in mma-FRAGMENT-major order:
// idx = warp*4096 + chunk*512 + g*128 + nt*32 + (gid*4+q); value = float2
__device__ float2   g_Bfrag[32768];
__device__ float    g_bias[256];           // interleaved: [2j]=bz_j, [2j+1]=bh_j
__device__ unsigned g_bar_count;
__device__ unsigned g_bar_gen;

// ---------------------------------------------------------------------------
// Software grid barrier (all FUSE_BLOCKS co-resident by __launch_bounds__).
// ---------------------------------------------------------------------------
__device__ __forceinline__ void grid_barrier() {
    __threadfence();
    __syncthreads();
    if (threadIdx.x == 0) {
        unsigned gen = *(volatile unsigned*)&g_bar_gen;
        unsigned t = atomicAdd(&g_bar_count, 1u);
        if (t == (unsigned)gridDim.x - 1u) {
            *(volatile unsigned*)&g_bar_count = 0u;
            __threadfence();
            atomicAdd(&g_bar_gen, 1u);
        } else {
            while (*(volatile unsigned*)&g_bar_gen == gen) { }
            __threadfence();
        }
    }
    __syncthreads();
}

__device__ __forceinline__ float tf32_rna(float v) {
    uint32_t r;
    asm("cvt.rna.tf32.f32 %0, %1;" : "=r"(r) : "f"(v));
    return __uint_as_float(r);
}

// ---------------------------------------------------------------------------
// Warp-per-node fp16 gather body
// ---------------------------------------------------------------------------
__device__ __forceinline__ float2 gather_f16(const __half* __restrict__ in,
                                             int beg, int end, int lane) {
    float ax = 0.f, ay = 0.f;
    int e = beg;
    for (; e + 4 <= end; e += 4) {
        int2 m0 = __ldg(g_meta + e),     m1 = __ldg(g_meta + e + 1);
        int2 m2 = __ldg(g_meta + e + 2), m3 = __ldg(g_meta + e + 3);
        float2 v0 = __half22float2(__ldg(reinterpret_cast<const __half2*>(in + m0.x * 64) + lane));
        float2 v1 = __half22float2(__ldg(reinterpret_cast<const __half2*>(in + m1.x * 64) + lane));
        float2 v2 = __half22float2(__ldg(reinterpret_cast<const __half2*>(in + m2.x * 64) + lane));
        float2 v3 = __half22float2(__ldg(reinterpret_cast<const __half2*>(in + m3.x * 64) + lane));
        float w0 = __int_as_float(m0.y), w1 = __int_as_float(m1.y);
        float w2 = __int_as_float(m2.y), w3 = __int_as_float(m3.y);
        ax += w0 * v0.x + w1 * v1.x + w2 * v2.x + w3 * v3.x;
        ay += w0 * v0.y + w1 * v1.y + w2 * v2.y + w3 * v3.y;
    }
    for (; e < end; e++) {
        int2 m = __ldg(g_meta + e);
        float2 v = __half22float2(__ldg(reinterpret_cast<const __half2*>(in + m.x * 64) + lane));
        float w = __int_as_float(m.y);
        ax += w * v.x; ay += w * v.y;
    }
    return make_float2(ax, ay);
}

// ---------------------------------------------------------------------------
// Fused preprocessing + propagation (persistent; software grid barriers).
// ---------------------------------------------------------------------------
__global__ __launch_bounds__(FUSE_THREADS, 4)
void k_fused(const float* __restrict__ x,
             const int* __restrict__ ei, const float* __restrict__ ew,
             const float* __restrict__ Wxz, const float* __restrict__ Wxh,
             const float* __restrict__ bxz, const float* __restrict__ bhz,
             const float* __restrict__ bxh, const float* __restrict__ bhh,
             int n, int e) {
    __shared__ int s_ws[32];
    __shared__ int s_pref[2];

    int t = threadIdx.x;
    int gtid = blockIdx.x * FUSE_THREADS + t;
    int gstride = gridDim.x * FUSE_THREADS;
    int lane = t & 31, wrp = t >> 5;
    int nchunk = (n + FUSE_THREADS - 1) / FUSE_THREADS;

    // ---- Phase A: Bfrag build / bias / x->fp16 copy  ||  deg + histogram ----
    for (int idx = gtid; idx < 32768; idx += gstride) {
        int w  = idx >> 12;
        int c  = (idx >> 9) & 7;
        int g  = (idx >> 7) & 3;
        int nt = (idx >> 5) & 3;
        int l2 = idx & 31;
        int gid2 = l2 >> 2, q2 = l2 & 3;
        int np = w * 32 + nt * 8 + gid2;
        int j = np >> 1;
        int k0 = c * 32 + g * 8 + q2, k1 = k0 + 4;
        const float* W = (np & 1) ? Wxh : Wxz;
        float v0 = W[(k0 >> 6) * 64 * 128 + (k0 & 63) * 128 + j];
        float v1 = W[(k1 >> 6) * 64 * 128 + (k1 & 63) * 128 + j];
        g_Bfrag[idx] = make_float2(tf32_rna(v0), tf32_rna(v1));
    }
    if (gtid < 256) {
        int j = gtid >> 1;
        g_bias[gtid] = (gtid & 1) ? (bxh[j] + bhh[j]) : (bxz[j] + bhz[j]);
    }
    {
        int n2 = n * 32;  // __half2 count
        const float2* x2 = reinterpret_cast<const float2*>(x);
        __half2* xh2 = reinterpret_cast<__half2*>(g_Xh);
        for (int i = gtid; i < n2; i += gstride) {
            float2 v = __ldg(x2 + i);
            xh2[i] = __floats2half2_rn(v.x, v.y);
        }
    }
    for (int i = gtid; i < e; i += gstride) {
        int s = ei[i], d = ei[e + i];
        if (s != d) atomicAdd(&g_dis[s], ew[i]);
        atomicAdd(&g_cnt[d], 1);
    }
    grid_barrier();

    // ---- Phase B: per-chunk local scan of cnt; finalize d^{-1/2} ----
    for (int c = blockIdx.x; c < nchunk; c += gridDim.x) {
        int i = c * FUSE_THREADS + t;
        int v = (i < n) ? g_cnt[i] : 0;
        if (i < n) {
            float dg = g_dis[i];
            g_dis[i] = (dg > 0.f) ? rsqrtf(dg) : 0.f;
        }
        if (t < 32) s_ws[t] = 0;
        __syncthreads();
        int s = v;
#pragma unroll
        for (int o = 1; o < 32; o <<= 1) {
            int u = __shfl_up_sync(0xffffffffu, s, o);
            if (lane >= o) s += u;
        }
        if (lane == 31) s_ws[wrp] = s;
        __syncthreads();
        if (wrp == 0) {
            int u = s_ws[lane];
#pragma unroll
            for (int o = 1; o < 32; o <<= 1) {
                int z = __shfl_up_sync(0xffffffffu, u, o);
                if (lane >= o) u += z;
            }
            s_ws[lane] = u;
        }
        __syncthreads();
        int excl = (s - v) + (wrp ? s_ws[wrp - 1] : 0);
        if (i < n) g_row[i] = excl;
        if (t == FUSE_THREADS - 1) g_blksum[c] = excl + v;
        __syncthreads();
    }
    grid_barrier();

    // ---- Phase C: add chunk prefixes; init cursors; reset cnt ----
    for (int c = blockIdx.x; c < nchunk; c += gridDim.x) {
        if (t < 32) {
            int sum_lt = 0, sum_all = 0;
            for (int j = t; j < nchunk; j += 32) {
                int v = g_blksum[j];
                sum_all += v;
                if (j < c) sum_lt += v;
            }
#pragma unroll
            for (int o = 16; o > 0; o >>= 1) {
                sum_lt  += __shfl_xor_sync(0xffffffffu, sum_lt, o);
                sum_all += __shfl_xor_sync(0xffffffffu, sum_all, o);
            }
            if (t == 0) { s_pref[0] = sum_lt; s_pref[1] = sum_all; }
        }
        __syncthreads();
        int i = c * FUSE_THREADS + t;
        if (i < n) {
            int r = g_row[i] + s_pref[0];
            g_row[i] = r;
            g_cur[i] = r;
            g_cnt[i] = 0;
        }
        if (c == 0 && t == 0) g_row[n] = s_pref[1];
        __syncthreads();
    }
    grid_barrier();

    // ---- Phase D: normalized weights + CSR meta scatter ----
    for (int i = gtid; i < e; i += gstride) {
        int s = ei[i], d = ei[e + i];
        float w = (s == d) ? 0.f : -g_dis[s] * ew[i] * g_dis[d];
        int pos = atomicAdd(&g_cur[d], 1);
        g_meta[pos] = make_int2(s, __float_as_int(w));
    }
    grid_barrier();

    // ---- Phase E: S1 = P x (fp16 in/out); reset dis ----
    for (int i = gtid; i < n; i += gstride) g_dis[i] = 0.0f;
    int gwarp = (blockIdx.x * FUSE_THREADS + t) >> 5;
    int nwarps = (gridDim.x * FUSE_THREADS) >> 5;
    for (int node = gwarp; node < n; node += nwarps) {
        float2 r = gather_f16(g_Xh, g_row[node], g_row[node + 1], lane);
        reinterpret_cast<__half2*>(g_S1h + node * 64)[lane] = __floats2half2_rn(r.x, r.y);
    }
    grid_barrier();

    // ---- Phase F: S2 = P S1 (fp16 out) ----
    for (int node = gwarp; node < n; node += nwarps) {
        float2 r = gather_f16(g_S1h, g_row[node], g_row[node + 1], lane);
        reinterpret_cast<__half2*>(g_S2h + node * 64)[lane] = __floats2half2_rn(r.x, r.y);
    }
    grid_barrier();

    // ---- Phase G: S3 = P S2 (fp32 out) ----
    for (int node = gwarp; node < n; node += nwarps) {
        float2 r = gather_f16(g_S2h, g_row[node], g_row[node + 1], lane);
        reinterpret_cast<float2*>(g_S3 + node * 64)[lane] = r;
    }
}

// ---------------------------------------------------------------------------
// Persistent tf32 mma GEMM, tile 64(M) x 256(N), 256 threads, 2 CTAs/SM,
// grid = 592 (exactly 2 full waves). A staged once per tile into smem;
// B fragments loaded directly from fragment-major global (L2-resident).
// ---------------------------------------------------------------------------
#define GA_STRIDE 264
#define SM_A_FLOATS (64 * GA_STRIDE)
#define SM_RED_FLOATS (64 * 8)
#define GEMM_SMEM ((SM_A_FLOATS + SM_RED_FLOATS) * 4)

__device__ __forceinline__ void mma_tf32(float* d, uint32_t a0, uint32_t a1,
                                         uint32_t a2, uint32_t a3,
                                         uint32_t b0, uint32_t b1) {
    asm volatile(
        "mma.sync.aligned.m16n8k8.row.col.f32.tf32.tf32.f32 "
        "{%0,%1,%2,%3}, {%4,%5,%6,%7}, {%8,%9}, {%0,%1,%2,%3};"
        : "+f"(d[0]), "+f"(d[1]), "+f"(d[2]), "+f"(d[3])
        : "r"(a0), "r"(a1), "r"(a2), "r"(a3), "r"(b0), "r"(b1));
}

__device__ __forceinline__ void load8h(const __half* p, float* f) {
    int4 raw = __ldg(reinterpret_cast<const int4*>(p));
    __half2 h0 = *reinterpret_cast<__half2*>(&raw.x);
    __half2 h1 = *reinterpret_cast<__half2*>(&raw.y);
    __half2 h2 = *reinterpret_cast<__half2*>(&raw.z);
    __half2 h3 = *reinterpret_cast<__half2*>(&raw.w);
    float2 a = __half22float2(h0), b = __half22float2(h1);
    float2 c = __half22float2(h2), d = __half22float2(h3);
    f[0] = a.x; f[1] = a.y; f[2] = b.x; f[3] = b.y;
    f[4] = c.x; f[5] = c.y; f[6] = d.x; f[7] = d.y;
}

__global__ __launch_bounds__(256, 2) void k_gemm_mma(const float* __restrict__ x,
                                                     const float* __restrict__ linW,
                                                     const float* __restrict__ linb,
                                                     float* __restrict__ out, int n) {
    extern __shared__ __align__(16) float smem[];
    float* As  = smem;                       // [64][GA_STRIDE] full K, permuted
    float* red = As + SM_A_FLOATS;           // [64][8]

    int tid  = threadIdx.x;
    int warp = tid >> 5;                     // 0..7 = n-slice
    int lane = tid & 31;
    int gid = lane >> 2;
    int q   = lane & 3;

    // per-thread constants (tile-invariant)
    float bz[4], bh[4], lw[4];
#pragma unroll
    for (int nt = 0; nt < 4; nt++) {
        int j = warp * 16 + nt * 4 + q;
        bz[nt] = __ldg(g_bias + 2 * j);
        bh[nt] = __ldg(g_bias + 2 * j + 1);
        lw[nt] = __ldg(linW + j);
    }
    float lb = __ldg(linb);
    const float2* bwarp = g_Bfrag + warp * 4096 + lane;

    int ntiles = (n + 63) / 64;
    for (int tile = blockIdx.x; tile < ntiles; tile += gridDim.x) {
        int rbase = tile * 64;

        // ---- stage FULL A tile: rows 0..63, all 8 k-chunks, permuted ----
        {
            int a_row  = tid >> 2;
            int a_quad = tid & 3;
            int grow = rbase + a_row;
#pragma unroll
            for (int cc = 0; cc < 8; cc++) {
                int kb = cc >> 1;
                int f0 = (cc & 1) * 32 + a_quad * 8;
                float* dst = As + a_row * GA_STRIDE + cc * 32 + a_quad * 8;
                if (grow < n) {
                    long off = (long)grow * 64 + f0;
                    float fv[8];
                    if (kb == 0) {
                        float4 v1 = __ldg(reinterpret_cast<const float4*>(x + off));
                        float4 v2 = __ldg(reinterpret_cast<const float4*>(x + off + 4));
                        fv[0] = v1.x; fv[1] = v1.y; fv[2] = v1.z; fv[3] = v1.w;
                        fv[4] = v2.x; fv[5] = v2.y; fv[6] = v2.z; fv[7] = v2.w;
                    } else if (kb == 1) {
                        load8h(g_S1h + off, fv);
                    } else if (kb == 2) {
                        load8h(g_S2h + off, fv);
                        float4 b1 = __ldg(reinterpret_cast<const float4*>(x + off));
                        float4 b2 = __ldg(reinterpret_cast<const float4*>(x + off + 4));
                        fv[0] = 2.f * fv[0] - b1.x; fv[1] = 2.f * fv[1] - b1.y;
                        fv[2] = 2.f * fv[2] - b1.z; fv[3] = 2.f * fv[3] - b1.w;
                        fv[4] = 2.f * fv[4] - b2.x; fv[5] = 2.f * fv[5] - b2.y;
                        fv[6] = 2.f * fv[6] - b2.z; fv[7] = 2.f * fv[7] - b2.w;
                    } else {
                        float s1[8];
                        load8h(g_S1h + off, s1);
                        float4 a1 = __ldg(reinterpret_cast<const float4*>(g_S3 + off));
                        float4 a2 = __ldg(reinterpret_cast<const float4*>(g_S3 + off + 4));
                        fv[0] = 4.f * a1.x - 3.f * s1[0]; fv[1] = 4.f * a1.y - 3.f * s1[1];
                        fv[2] = 4.f * a1.z - 3.f * s1[2]; fv[3] = 4.f * a1.w - 3.f * s1[3];
                        fv[4] = 4.f * a2.x - 3.f * s1[4]; fv[5] = 4.f * a2.y - 3.f * s1[5];
                        fv[6] = 4.f * a2.z - 3.f * s1[6]; fv[7] = 4.f * a2.w - 3.f * s1[7];
                    }
                    float4 o0 = make_float4(tf32_rna(fv[0]), tf32_rna(fv[4]),
                                            tf32_rna(fv[1]), tf32_rna(fv[5]));
                    float4 o1 = make_float4(tf32_rna(fv[2]), tf32_rna(fv[6]),
                                            tf32_rna(fv[3]), tf32_rna(fv[7]));
                    *reinterpret_cast<float4*>(dst)     = o0;
                    *reinterpret_cast<float4*>(dst + 4) = o1;
                } else {
                    float4 z = make_float4(0.f, 0.f, 0.f, 0.f);
                    *reinterpret_cast<float4*>(dst)     = z;
                    *reinterpret_cast<float4*>(dst + 4) = z;
                }
            }
        }
        __syncthreads();

        float acc[4][4][4];
#pragma unroll
        for (int mt = 0; mt < 4; mt++)
#pragma unroll
            for (int nt = 0; nt < 4; nt++)
#pragma unroll
                for (int c = 0; c < 4; c++) acc[mt][nt][c] = 0.f;

        // ---- K loop: no syncs, no staging ----
        for (int c = 0; c < 8; c++) {
#pragma unroll
            for (int g = 0; g < 4; g++) {
                uint32_t af[4][4];
#pragma unroll
                for (int mt = 0; mt < 4; mt++) {
                    int r0 = mt * 16 + gid;
                    float2 lo = *reinterpret_cast<const float2*>(As + r0 * GA_STRIDE + c * 32 + g * 8 + q * 2);
                    float2 hi = *reinterpret_cast<const float2*>(As + (r0 + 8) * GA_STRIDE + c * 32 + g * 8 + q * 2);
                    af[mt][0] = __float_as_uint(lo.x);
                    af[mt][2] = __float_as_uint(lo.y);
                    af[mt][1] = __float_as_uint(hi.x);
                    af[mt][3] = __float_as_uint(hi.y);
                }
                const float2* bp = bwarp + c * 512 + g * 128;
#pragma unroll
                for (int nt = 0; nt < 4; nt++) {
                    float2 b = __ldg(bp + nt * 32);
                    uint32_t b0 = __float_as_uint(b.x);
                    uint32_t b1 = __float_as_uint(b.y);
#pragma unroll
                    for (int mt = 0; mt < 4; mt++)
                        mma_tf32(acc[mt][nt], af[mt][0], af[mt][1], af[mt][2], af[mt][3], b0, b1);
                }
            }
        }

        // ---- fused epilogue ----
#pragma unroll
        for (int mt = 0; mt < 4; mt++) {
#pragma unroll
            for (int half = 0; half < 2; half++) {
                float p = 0.f;
#pragma unroll
                for (int nt = 0; nt < 4; nt++) {
                    float z = acc[mt][nt][half * 2 + 0] + bz[nt];
                    float h = acc[mt][nt][half * 2 + 1] + bh[nt];
                    float th;
                    asm("tanh.approx.f32 %0, %1;" : "=f"(th) : "f"(h));
                    float sg = 1.0f / (1.0f + __expf(z));  // sigmoid(-z)
                    p += fmaxf(sg * th, 0.f) * lw[nt];
                }
                p += __shfl_xor_sync(0xffffffffu, p, 1);
                p += __shfl_xor_sync(0xffffffffu, p, 2);
                if (q == 0) {
                    int row = mt * 16 + half * 8 + gid;   // 0..63
                    red[row * 8 + warp] = p;
                }
            }
        }
        __syncthreads();
        if (tid < 64) {
            int row = rbase + tid;
            if (row < n) {
                float s = 0.f;
#pragma unroll
                for (int w = 0; w < 8; w++) s += red[tid * 8 + w];
                out[row] = s + lb;
            }
        }
    }
}

// ---------------------------------------------------------------------------
// kernel_launch — exactly TWO kernel launches
// ---------------------------------------------------------------------------
extern "C" void kernel_launch(void* const* d_in, const int* in_sizes, int n_in,
                              void* d_out, int out_size) {
    (void)n_in; (void)out_size;
    const float* x    = (const float*)d_in[0];
    const int*   ei   = (const int*)d_in[1];
    const float* ew   = (const float*)d_in[2];
    const float* Wxz  = (const float*)d_in[3];
    const float* bxz  = (const float*)d_in[4];
    const float* bhz  = (const float*)d_in[6];
    const float* Wxh  = (const float*)d_in[11];
    const float* bxh  = (const float*)d_in[12];
    const float* bhh  = (const float*)d_in[14];
    const float* linW = (const float*)d_in[15];
    const float* linb = (const float*)d_in[16];
    float* out = (float*)d_out;

    int n = in_sizes[0] / FIN;   // 50000
    int e = in_sizes[2];         // 600000

    // 1) fused preprocess + Chebyshev power props (persistent, grid barriers)
    k_fused<<<FUSE_BLOCKS, FUSE_THREADS>>>(x, ei, ew, Wxz, Wxh,
                                           bxz, bhz, bxh, bhh, n, e);

    // 2) persistent tf32 mma GEMM + GRU epilogue + linear head
    cudaFuncSetAttribute(k_gemm_mma, cudaFuncAttributeMaxDynamicSharedMemorySize,
                         GEMM_SMEM);
    k_gemm_mma<<<GEMM_BLOCKS, 256, GEMM_SMEM>>>(x, linW, linb, out, n);
}

// round 16
// speedup vs baseline: 1.0158x; 1.0158x over previous
#include <cuda_runtime.h>
#include <cuda_fp16.h>
#include <cstdint>
#include <math.h>

// Problem constants (fixed by the dataset)
#define NMAX 50000
#define EMAX 600000
#define FIN  64
#define HID  128

#define FUSE_BLOCKS 592        // 4 blocks/SM x 148 SMs, residency-guaranteed
#define FUSE_THREADS 256

// ---------------------------------------------------------------------------
// Scratch (device globals; no allocation allowed in kernel_launch)
// Replay invariants: g_cnt==0, g_dis==0, g_total==0, g_bar_count==0 at entry.
// ---------------------------------------------------------------------------
__device__ float    g_dis[NMAX];           // deg, then d^{-1/2}, then reset to 0
__device__ int      g_cnt[NMAX];           // in-degree histogram; reset to 0
__device__ int      g_cur[NMAX];           // scatter cursors
__device__ int      g_row[NMAX];           // CSR range begin (unordered bases)
__device__ int      g_rowend[NMAX];        // CSR range end
__device__ int      g_total;               // base allocator; reset to 0
__device__ int2     g_meta[EMAX];          // per-edge {src, w_bits} (CSR order)
__device__ __half   g_Xh[NMAX * FIN];      // fp16 copy of x (gather source only)
__device__ __half   g_S1h[NMAX * FIN];     // P x      (fp16 storage)
__device__ __half   g_S2h[NMAX * FIN];     // P^2 x    (fp16 storage)
__device__ float    g_S3[NMAX * FIN];      // P^3 x    (fp32)
// B operand in mma-FRAGMENT-major order:
// idx = warp*4096 + chunk*512 + g*128 + nt*32 + (gid*4+q); value = float2
__device__ float2   g_Bfrag[32768];
__device__ float    g_bias[256];           // interleaved: [2j]=bz_j, [2j+1]=bh_j
__device__ unsigned g_bar_count;
__device__ unsigned g_bar_gen;

// ---------------------------------------------------------------------------
// Software grid barrier (all FUSE_BLOCKS co-resident by __launch_bounds__).
// ---------------------------------------------------------------------------
__device__ __forceinline__ void grid_barrier() {
    __threadfence();
    __syncthreads();
    if (threadIdx.x == 0) {
        unsigned gen = *(volatile unsigned*)&g_bar_gen;
        unsigned t = atomicAdd(&g_bar_count, 1u);
        if (t == (unsigned)gridDim.x - 1u) {
            *(volatile unsigned*)&g_bar_count = 0u;
            __threadfence();
            atomicAdd(&g_bar_gen, 1u);
        } else {
            while (*(volatile unsigned*)&g_bar_gen == gen) { }
            __threadfence();
        }
    }
    __syncthreads();
}

__device__ __forceinline__ float tf32_rna(float v) {
    uint32_t r;
    asm("cvt.rna.tf32.f32 %0, %1;" : "=r"(r) : "f"(v));
    return __uint_as_float(r);
}

// ---------------------------------------------------------------------------
// Warp-per-node fp16 gather body
// ---------------------------------------------------------------------------
__device__ __forceinline__ float2 gather_f16(const __half* __restrict__ in,
                                             int beg, int end, int lane) {
    float ax = 0.f, ay = 0.f;
    int e = beg;
    for (; e + 4 <= end; e += 4) {
        int2 m0 = __ldg(g_meta + e),     m1 = __ldg(g_meta + e + 1);
        int2 m2 = __ldg(g_meta + e + 2), m3 = __ldg(g_meta + e + 3);
        float2 v0 = __half22float2(__ldg(reinterpret_cast<const __half2*>(in + m0.x * 64) + lane));
        float2 v1 = __half22float2(__ldg(reinterpret_cast<const __half2*>(in + m1.x * 64) + lane));
        float2 v2 = __half22float2(__ldg(reinterpret_cast<const __half2*>(in + m2.x * 64) + lane));
        float2 v3 = __half22float2(__ldg(reinterpret_cast<const __half2*>(in + m3.x * 64) + lane));
        float w0 = __int_as_float(m0.y), w1 = __int_as_float(m1.y);
        float w2 = __int_as_float(m2.y), w3 = __int_as_float(m3.y);
        ax += w0 * v0.x + w1 * v1.x + w2 * v2.x + w3 * v3.x;
        ay += w0 * v0.y + w1 * v1.y + w2 * v2.y + w3 * v3.y;
    }
    for (; e < end; e++) {
        int2 m = __ldg(g_meta + e);
        float2 v = __half22float2(__ldg(reinterpret_cast<const __half2*>(in + m.x * 64) + lane));
        float w = __int_as_float(m.y);
        ax += w * v.x; ay += w * v.y;
    }
    return make_float2(ax, ay);
}

// ---------------------------------------------------------------------------
// Fused preprocessing + propagation (persistent; software grid barriers).
// ---------------------------------------------------------------------------
__global__ __launch_bounds__(FUSE_THREADS, 4)
void k_fused(const float* __restrict__ x,
             const int* __restrict__ ei, const float* __restrict__ ew,
             const float* __restrict__ Wxz, const float* __restrict__ Wxh,
             const float* __restrict__ bxz, const float* __restrict__ bhz,
             const float* __restrict__ bxh, const float* __restrict__ bhh,
             int n, int e) {
    __shared__ int s_ws[32];
    __shared__ int s_base;

    int t = threadIdx.x;
    int gtid = blockIdx.x * FUSE_THREADS + t;
    int gstride = gridDim.x * FUSE_THREADS;
    int lane = t & 31, wrp = t >> 5;
    int nchunk = (n + FUSE_THREADS - 1) / FUSE_THREADS;

    // ---- Phase A: Bfrag build / bias / x->fp16 copy  ||  deg + histogram ----
    for (int idx = gtid; idx < 32768; idx += gstride) {
        int w  = idx >> 12;
        int c  = (idx >> 9) & 7;
        int g  = (idx >> 7) & 3;
        int nt = (idx >> 5) & 3;
        int l2 = idx & 31;
        int gid2 = l2 >> 2, q2 = l2 & 3;
        int np = w * 32 + nt * 8 + gid2;
        int j = np >> 1;
        int k0 = c * 32 + g * 8 + q2, k1 = k0 + 4;
        const float* W = (np & 1) ? Wxh : Wxz;
        float v0 = W[(k0 >> 6) * 64 * 128 + (k0 & 63) * 128 + j];
        float v1 = W[(k1 >> 6) * 64 * 128 + (k1 & 63) * 128 + j];
        g_Bfrag[idx] = make_float2(tf32_rna(v0), tf32_rna(v1));
    }
    if (gtid < 256) {
        int j = gtid >> 1;
        g_bias[gtid] = (gtid & 1) ? (bxh[j] + bhh[j]) : (bxz[j] + bhz[j]);
    }
    {
        int n2 = n * 32;  // __half2 count
        const float2* x2 = reinterpret_cast<const float2*>(x);
        __half2* xh2 = reinterpret_cast<__half2*>(g_Xh);
        for (int i = gtid; i < n2; i += gstride) {
            float2 v = __ldg(x2 + i);
            xh2[i] = __floats2half2_rn(v.x, v.y);
        }
    }
    for (int i = gtid; i < e; i += gstride) {
        int s = ei[i], d = ei[e + i];
        if (s != d) atomicAdd(&g_dis[s], ew[i]);
        atomicAdd(&g_cnt[d], 1);
    }
    grid_barrier();

    // ---- Phase B': local scan + unordered base alloc; cursors; row_end;
    //      cnt reset; finalize d^{-1/2}.  (CSR ranges need not be ordered.) ----
    for (int c = blockIdx.x; c < nchunk; c += gridDim.x) {
        int i = c * FUSE_THREADS + t;
        int v = 0;
        if (i < n) {
            v = g_cnt[i];
            float dg = g_dis[i];
            g_dis[i] = (dg > 0.f) ? rsqrtf(dg) : 0.f;
        }
        if (t < 32) s_ws[t] = 0;
        __syncthreads();
        int s = v;
#pragma unroll
        for (int o = 1; o < 32; o <<= 1) {
            int u = __shfl_up_sync(0xffffffffu, s, o);
            if (lane >= o) s += u;
        }
        if (lane == 31) s_ws[wrp] = s;
        __syncthreads();
        if (wrp == 0) {
            int u = s_ws[lane];
#pragma unroll
            for (int o = 1; o < 32; o <<= 1) {
                int z = __shfl_up_sync(0xffffffffu, u, o);
                if (lane >= o) u += z;
            }
            s_ws[lane] = u;
        }
        __syncthreads();
        int excl = (s - v) + (wrp ? s_ws[wrp - 1] : 0);
        if (t == 0) s_base = atomicAdd(&g_total, s_ws[7]);   // 8 warps/block
        __syncthreads();
        if (i < n) {
            int beg = s_base + excl;
            g_row[i] = beg;
            g_cur[i] = beg;
            g_rowend[i] = beg + v;
            g_cnt[i] = 0;                                    // replay invariant
        }
        __syncthreads();
    }
    grid_barrier();

    // ---- Phase D: normalized weights + CSR meta scatter; reset g_total ----
    if (gtid == 0) g_total = 0;                              // replay invariant
    for (int i = gtid; i < e; i += gstride) {
        int s = ei[i], d = ei[e + i];
        float w = (s == d) ? 0.f : -g_dis[s] * ew[i] * g_dis[d];
        int pos = atomicAdd(&g_cur[d], 1);
        g_meta[pos] = make_int2(s, __float_as_int(w));
    }
    grid_barrier();

    // ---- Phase E: S1 = P x (fp16 in/out); reset dis ----
    for (int i = gtid; i < n; i += gstride) g_dis[i] = 0.0f;
    int gwarp = (blockIdx.x * FUSE_THREADS + t) >> 5;
    int nwarps = (gridDim.x * FUSE_THREADS) >> 5;
    for (int node = gwarp; node < n; node += nwarps) {
        float2 r = gather_f16(g_Xh, g_row[node], g_rowend[node], lane);
        reinterpret_cast<__half2*>(g_S1h + node * 64)[lane] = __floats2half2_rn(r.x, r.y);
    }
    grid_barrier();

    // ---- Phase F: S2 = P S1 (fp16 out) ----
    for (int node = gwarp; node < n; node += nwarps) {
        float2 r = gather_f16(g_S1h, g_row[node], g_rowend[node], lane);
        reinterpret_cast<__half2*>(g_S2h + node * 64)[lane] = __floats2half2_rn(r.x, r.y);
    }
    grid_barrier();

    // ---- Phase G: S3 = P S2 (fp32 out) ----
    for (int node = gwarp; node < n; node += nwarps) {
        float2 r = gather_f16(g_S2h, g_row[node], g_rowend[node], lane);
        reinterpret_cast<float2*>(g_S3 + node * 64)[lane] = r;
    }
}

// ---------------------------------------------------------------------------
// tf32 mma GEMM, tile 64(M) x 256(N), 256 threads, 2 CTAs/SM, grid 782.
// A staged once (full K=256) with PAIRED fragment layout: within each 32-k
// chunk, a thread's fragments for groups (2gg, 2gg+1) are 16B-contiguous:
//   addr = c*32 + gg*16 + q*4 + (g&1)*2 + {k=q, k=q+4}
// -> one LDS.128 yields both groups' fragments. B fragment-major from L2.
// ---------------------------------------------------------------------------
#define GA_STRIDE 264
#define SM_A_FLOATS (64 * GA_STRIDE)
#define SM_RED_FLOATS (64 * 8)
#define GEMM_SMEM ((SM_A_FLOATS + SM_RED_FLOATS) * 4)

__device__ __forceinline__ void mma_tf32(float* d, uint32_t a0, uint32_t a1,
                                         uint32_t a2, uint32_t a3,
                                         uint32_t b0, uint32_t b1) {
    asm volatile(
        "mma.sync.aligned.m16n8k8.row.col.f32.tf32.tf32.f32 "
        "{%0,%1,%2,%3}, {%4,%5,%6,%7}, {%8,%9}, {%0,%1,%2,%3};"
        : "+f"(d[0]), "+f"(d[1]), "+f"(d[2]), "+f"(d[3])
        : "r"(a0), "r"(a1), "r"(a2), "r"(a3), "r"(b0), "r"(b1));
}

__device__ __forceinline__ void load8h(const __half* p, float* f) {
    int4 raw = __ldg(reinterpret_cast<const int4*>(p));
    __half2 h0 = *reinterpret_cast<__half2*>(&raw.x);
    __half2 h1 = *reinterpret_cast<__half2*>(&raw.y);
    __half2 h2 = *reinterpret_cast<__half2*>(&raw.z);
    __half2 h3 = *reinterpret_cast<__half2*>(&raw.w);
    float2 a = __half22float2(h0), b = __half22float2(h1);
    float2 c = __half22float2(h2), d = __half22float2(h3);
    f[0] = a.x; f[1] = a.y; f[2] = b.x; f[3] = b.y;
    f[4] = c.x; f[5] = c.y; f[6] = d.x; f[7] = d.y;
}

__global__ __launch_bounds__(256, 2) void k_gemm_mma(const float* __restrict__ x,
                                                     const float* __restrict__ linW,
                                                     const float* __restrict__ linb,
                                                     float* __restrict__ out, int n) {
    extern __shared__ __align__(16) float smem[];
    float* As  = smem;                       // [64][GA_STRIDE] full K, paired
    float* red = As + SM_A_FLOATS;           // [64][8]

    int tid  = threadIdx.x;
    int warp = tid >> 5;                     // 0..7 = n-slice
    int lane = tid & 31;
    int gid = lane >> 2;
    int q   = lane & 3;
    int rbase = blockIdx.x * 64;

    // ---- stage FULL A tile once: rows 0..63, paired fragment layout ----
    {
        int a_row  = tid >> 2;
        int a_quad = tid & 3;                // k-group g within chunk
        int grow = rbase + a_row;
#pragma unroll
        for (int cc = 0; cc < 8; cc++) {
            int kb = cc >> 1;
            int f0 = (cc & 1) * 32 + a_quad * 8;
            float* dst = As + a_row * GA_STRIDE + cc * 32
                       + (a_quad >> 1) * 16 + (a_quad & 1) * 2;
            float fv[8];
            if (grow < n) {
                long off = (long)grow * 64 + f0;
                if (kb == 0) {
                    float4 v1 = __ldg(reinterpret_cast<const float4*>(x + off));
                    float4 v2 = __ldg(reinterpret_cast<const float4*>(x + off + 4));
                    fv[0] = v1.x; fv[1] = v1.y; fv[2] = v1.z; fv[3] = v1.w;
                    fv[4] = v2.x; fv[5] = v2.y; fv[6] = v2.z; fv[7] = v2.w;
                } else if (kb == 1) {
                    load8h(g_S1h + off, fv);
                } else if (kb == 2) {
                    load8h(g_S2h + off, fv);
                    float4 b1 = __ldg(reinterpret_cast<const float4*>(x + off));
                    float4 b2 = __ldg(reinterpret_cast<const float4*>(x + off + 4));
                    fv[0] = 2.f * fv[0] - b1.x; fv[1] = 2.f * fv[1] - b1.y;
                    fv[2] = 2.f * fv[2] - b1.z; fv[3] = 2.f * fv[3] - b1.w;
                    fv[4] = 2.f * fv[4] - b2.x; fv[5] = 2.f * fv[5] - b2.y;
                    fv[6] = 2.f * fv[6] - b2.z; fv[7] = 2.f * fv[7] - b2.w;
                } else {
                    float s1[8];
                    load8h(g_S1h + off, s1);
                    float4 a1 = __ldg(reinterpret_cast<const float4*>(g_S3 + off));
                    float4 a2 = __ldg(reinterpret_cast<const float4*>(g_S3 + off + 4));
                    fv[0] = 4.f * a1.x - 3.f * s1[0]; fv[1] = 4.f * a1.y - 3.f * s1[1];
                    fv[2] = 4.f * a1.z - 3.f * s1[2]; fv[3] = 4.f * a1.w - 3.f * s1[3];
                    fv[4] = 4.f * a2.x - 3.f * s1[4]; fv[5] = 4.f * a2.y - 3.f * s1[5];
                    fv[6] = 4.f * a2.z - 3.f * s1[6]; fv[7] = 4.f * a2.w - 3.f * s1[7];
                }
            } else {
#pragma unroll
                for (int i = 0; i < 8; i++) fv[i] = 0.f;
            }
            // pair (fv[qq], fv[qq+4]) -> dst[qq*4 .. +1]
#pragma unroll
            for (int qq = 0; qq < 4; qq++) {
                *reinterpret_cast<float2*>(dst + qq * 4) =
                    make_float2(tf32_rna(fv[qq]), tf32_rna(fv[qq + 4]));
            }
        }
    }
    __syncthreads();

    float acc[4][4][4];
#pragma unroll
    for (int mt = 0; mt < 4; mt++)
#pragma unroll
        for (int nt = 0; nt < 4; nt++)
#pragma unroll
            for (int c = 0; c < 4; c++) acc[mt][nt][c] = 0.f;

    // ---- K loop: no syncs; paired A LDS.128, B fragments straight from L2 ----
    const float2* bwarp = g_Bfrag + warp * 4096 + lane;
    for (int c = 0; c < 8; c++) {
#pragma unroll
        for (int gg = 0; gg < 2; gg++) {
            float4 lo[4], hi[4];
#pragma unroll
            for (int mt = 0; mt < 4; mt++) {
                int r0 = mt * 16 + gid;
                lo[mt] = *reinterpret_cast<const float4*>(
                    As + r0 * GA_STRIDE + c * 32 + gg * 16 + q * 4);
                hi[mt] = *reinterpret_cast<const float4*>(
                    As + (r0 + 8) * GA_STRIDE + c * 32 + gg * 16 + q * 4);
            }
            const float2* bp = bwarp + c * 512 + (gg * 2) * 128;
#pragma unroll
            for (int nt = 0; nt < 4; nt++) {                 // g = 2gg
                float2 b = __ldg(bp + nt * 32);
                uint32_t b0 = __float_as_uint(b.x);
                uint32_t b1 = __float_as_uint(b.y);
#pragma unroll
                for (int mt = 0; mt < 4; mt++)
                    mma_tf32(acc[mt][nt],
                             __float_as_uint(lo[mt].x), __float_as_uint(hi[mt].x),
                             __float_as_uint(lo[mt].y), __float_as_uint(hi[mt].y),
                             b0, b1);
            }
#pragma unroll
            for (int nt = 0; nt < 4; nt++) {                 // g = 2gg+1
                float2 b = __ldg(bp + 128 + nt * 32);
                uint32_t b0 = __float_as_uint(b.x);
                uint32_t b1 = __float_as_uint(b.y);
#pragma unroll
                for (int mt = 0; mt < 4; mt++)
                    mma_tf32(acc[mt][nt],
                             __float_as_uint(lo[mt].z), __float_as_uint(hi[mt].z),
                             __float_as_uint(lo[mt].w), __float_as_uint(hi[mt].w),
                             b0, b1);
            }
        }
    }

    // ---- fused epilogue: thread's features j = warp*16 + nt*4 + q ----
    float bz[4], bh[4], lw[4];
#pragma unroll
    for (int nt = 0; nt < 4; nt++) {
        int j = warp * 16 + nt * 4 + q;
        bz[nt] = __ldg(g_bias + 2 * j);
        bh[nt] = __ldg(g_bias + 2 * j + 1);
        lw[nt] = __ldg(linW + j);
    }
#pragma unroll
    for (int mt = 0; mt < 4; mt++) {
#pragma unroll
        for (int half = 0; half < 2; half++) {
            float p = 0.f;
#pragma unroll
            for (int nt = 0; nt < 4; nt++) {
                float z = acc[mt][nt][half * 2 + 0] + bz[nt];
                float h = acc[mt][nt][half * 2 + 1] + bh[nt];
                float th;
                asm("tanh.approx.f32 %0, %1;" : "=f"(th) : "f"(h));
                float sg = 1.0f / (1.0f + __expf(z));  // sigmoid(-z)
                p += fmaxf(sg * th, 0.f) * lw[nt];
            }
            p += __shfl_xor_sync(0xffffffffu, p, 1);
            p += __shfl_xor_sync(0xffffffffu, p, 2);
            if (q == 0) {
                int row = mt * 16 + half * 8 + gid;   // 0..63
                red[row * 8 + warp] = p;
            }
        }
    }
    __syncthreads();
    if (tid < 64) {
        int row = rbase + tid;
        if (row < n) {
            float s = 0.f;
#pragma unroll
            for (int w = 0; w < 8; w++) s += red[tid * 8 + w];
            out[row] = s + __ldg(linb);
        }
    }
}

// ---------------------------------------------------------------------------
// kernel_launch — exactly TWO kernel launches
// ---------------------------------------------------------------------------
extern "C" void kernel_launch(void* const* d_in, const int* in_sizes, int n_in,
                              void* d_out, int out_size) {
    (void)n_in; (void)out_size;
    const float* x    = (const float*)d_in[0];
    const int*   ei   = (const int*)d_in[1];
    const float* ew   = (const float*)d_in[2];
    const float* Wxz  = (const float*)d_in[3];
    const float* bxz  = (const float*)d_in[4];
    const float* bhz  = (const float*)d_in[6];
    const float* Wxh  = (const float*)d_in[11];
    const float* bxh  = (const float*)d_in[12];
    const float* bhh  = (const float*)d_in[14];
    const float* linW = (const float*)d_in[15];
    const float* linb = (const float*)d_in[16];
    float* out = (float*)d_out;

    int n = in_sizes[0] / FIN;   // 50000
    int e = in_sizes[2];         // 600000

    // 1) fused preprocess + Chebyshev power props (persistent, grid barriers)
    k_fused<<<FUSE_BLOCKS, FUSE_THREADS>>>(x, ei, ew, Wxz, Wxh,
                                           bxz, bhz, bxh, bhh, n, e);

    // 2) tf32 mma GEMM + GRU epilogue + linear head (paired A fragments)
    cudaFuncSetAttribute(k_gemm_mma, cudaFuncAttributeMaxDynamicSharedMemorySize,
                         GEMM_SMEM);
    k_gemm_mma<<<(n + 63) / 64, 256, GEMM_SMEM>>>(x, linW, linb, out, n);
}